// round 7
// baseline (speedup 1.0000x reference)
#include <cuda_runtime.h>
#include <cuda_bf16.h>

// FeedForwardQuantum: out = relu(cos(x+theta) @ W1 + b1) @ W2 + b2
// B*S = 524288 tokens, E=8, F=32, all fp32.
//
// R6 strategy: all math stays on fma.rn.f32x2 / add.rn.f32x2 packed pairs.
//  - GEMM1 produces h packed over F-pairs.
//  - ReLU branch/unpack-free: relu(h) = (h + |h|) * 0.5, the 0.5 folded into
//    w2 at smem-fill (exact). |h| = 2x LOP3 on the alu pipe.
//  - GEMM2 accumulates over f-halves (acc_e holds partial sums in both
//    halves; final lo+hi fold per e). The relu'd F-pair feeds GEMM2 directly,
//    zero repacking.
//  - Transposed smem weights (contiguous over e) -> LDS.128 loads.

#define BLK 128
#define TPT 2

__device__ __forceinline__ unsigned long long pack2(float lo, float hi) {
    unsigned long long r;
    asm("mov.b64 %0, {%1, %2};" : "=l"(r) : "f"(lo), "f"(hi));
    return r;
}
__device__ __forceinline__ void unpack2(unsigned long long v, float& lo, float& hi) {
    asm("mov.b64 {%0, %1}, %2;" : "=f"(lo), "=f"(hi) : "l"(v));
}
__device__ __forceinline__ unsigned long long ffma2(unsigned long long a,
                                                    unsigned long long b,
                                                    unsigned long long c) {
    unsigned long long d;
    asm("fma.rn.f32x2 %0, %1, %2, %3;" : "=l"(d) : "l"(a), "l"(b), "l"(c));
    return d;
}
__device__ __forceinline__ unsigned long long fadd2(unsigned long long a,
                                                    unsigned long long b) {
    unsigned long long d;
    asm("add.rn.f32x2 %0, %1, %2;" : "=l"(d) : "l"(a), "l"(b));
    return d;
}

__global__ __launch_bounds__(BLK, 4)
void ffq_kernel(const float* __restrict__ x,
                const float* __restrict__ theta,
                const float* __restrict__ w1,   // [8, 32] row-major
                const float* __restrict__ b1,   // [32]
                const float* __restrict__ w2,   // [32, 8] row-major
                const float* __restrict__ b2,   // [8]
                float* __restrict__ out,
                int n_tok)
{
    // Transposed packed layouts (contiguous over e -> LDS.128):
    //  s_w1t[j][e] = (w1[e][2j],   w1[e][2j+1])          f-pair per e
    //  s_w2t[j][e] = 0.5*(w2[2j][e], w2[2j+1][e])        f-pair per e, prescaled
    __shared__ unsigned long long s_w1t[16][8];
    __shared__ unsigned long long s_w2t[16][8];
    __shared__ unsigned long long s_b1[16];
    __shared__ float s_b2[8];
    __shared__ float s_th[8];

    const int tid = threadIdx.x;

    // Cooperative fill (tiny, once per block).
    {
        const int j = tid >> 3;       // 0..15
        const int e = tid & 7;        // 0..7
        // w1[e][2j], w1[e][2j+1] are adjacent -> float2 load
        const float2 w1p = reinterpret_cast<const float2*>(w1 + e * 32 + 2 * j)[0];
        s_w1t[j][e] = pack2(w1p.x, w1p.y);
        // w2 rows 2j and 2j+1, column e (stride 8 apart), prescale by 0.5
        const float a = 0.5f * w2[(2 * j) * 8 + e];
        const float b = 0.5f * w2[(2 * j + 1) * 8 + e];
        s_w2t[j][e] = pack2(a, b);
    }
    if (tid < 16) {
        const float2 bp = reinterpret_cast<const float2*>(b1 + 2 * tid)[0];
        s_b1[tid] = pack2(bp.x, bp.y);
    }
    if (tid < 8) {
        s_b2[tid] = b2[tid];
        s_th[tid] = theta[tid];
    }
    __syncthreads();

    float th[8];
#pragma unroll
    for (int e = 0; e < 8; e++) th[e] = s_th[e];

    const unsigned long long ABS2 = 0x7FFFFFFF7FFFFFFFull;

    const long base = (long)blockIdx.x * (BLK * TPT) + tid;

    long tk[TPT];
    bool valid[TPT];
    unsigned long long qb[TPT][8];   // broadcast pairs (q_e, q_e)

#pragma unroll
    for (int k = 0; k < TPT; k++) {
        tk[k] = base + (long)k * BLK;
        valid[k] = (tk[k] < (long)n_tok);
        const long off = valid[k] ? tk[k] * 8 : 0;
        const float4 a0 = reinterpret_cast<const float4*>(x + off)[0];
        const float4 a1 = reinterpret_cast<const float4*>(x + off)[1];
        float q[8];
        q[0] = __cosf(a0.x + th[0]);
        q[1] = __cosf(a0.y + th[1]);
        q[2] = __cosf(a0.z + th[2]);
        q[3] = __cosf(a0.w + th[3]);
        q[4] = __cosf(a1.x + th[4]);
        q[5] = __cosf(a1.y + th[5]);
        q[6] = __cosf(a1.z + th[6]);
        q[7] = __cosf(a1.w + th[7]);
#pragma unroll
        for (int e = 0; e < 8; e++) qb[k][e] = pack2(q[e], q[e]);
    }

    // acc[k][e]: both halves hold partial f-sums; seed lo half with b2[e].
    unsigned long long acc[TPT][8];
#pragma unroll
    for (int k = 0; k < TPT; k++)
#pragma unroll
        for (int e = 0; e < 8; e++) acc[k][e] = pack2(s_b2[e], 0.0f);

    // Fused GEMM1 + packed-ReLU + f-paired GEMM2 over F-pairs j.
#pragma unroll
    for (int j = 0; j < 16; j++) {
        // Weight loads: contiguous u64[8] rows -> 2x LDS.128 each.
        unsigned long long w1p[8], w2p[8];
        {
            const ulonglong2* p1 = reinterpret_cast<const ulonglong2*>(s_w1t[j]);
            const ulonglong2* p2 = reinterpret_cast<const ulonglong2*>(s_w2t[j]);
#pragma unroll
            for (int i = 0; i < 4; i++) {
                ulonglong2 v1 = p1[i];
                w1p[2 * i] = v1.x; w1p[2 * i + 1] = v1.y;
                ulonglong2 v2 = p2[i];
                w2p[2 * i] = v2.x; w2p[2 * i + 1] = v2.y;
            }
        }
        const unsigned long long b1p = s_b1[j];

#pragma unroll
        for (int k = 0; k < TPT; k++) {
            // GEMM1: h = (h_{2j}, h_{2j+1})
            unsigned long long h = b1p;
#pragma unroll
            for (int e = 0; e < 8; e++) h = ffma2(qb[k][e], w1p[e], h);
            // Packed ReLU*2: r = h + |h|   (w2 carries the 0.5)
            const unsigned long long r = fadd2(h, h & ABS2);
            // GEMM2 over f-halves: acc_e += r .* w2pair_e
#pragma unroll
            for (int e = 0; e < 8; e++)
                acc[k][e] = ffma2(r, w2p[e], acc[k][e]);
        }
    }

    // Epilogue: out_e = lo(acc_e) + hi(acc_e)   (lo was seeded with b2_e)
#pragma unroll
    for (int k = 0; k < TPT; k++) {
        if (valid[k]) {
            float o[8];
#pragma unroll
            for (int e = 0; e < 8; e++) {
                float lo, hi;
                unpack2(acc[k][e], lo, hi);
                o[e] = lo + hi;
            }
            float4* dst = reinterpret_cast<float4*>(out + tk[k] * 8);
            dst[0] = make_float4(o[0], o[1], o[2], o[3]);
            dst[1] = make_float4(o[4], o[5], o[6], o[7]);
        }
    }
}

extern "C" void kernel_launch(void* const* d_in, const int* in_sizes, int n_in,
                              void* d_out, int out_size) {
    const float* x     = (const float*)d_in[0];
    const float* theta = (const float*)d_in[1];
    const float* w1    = (const float*)d_in[2];
    const float* b1    = (const float*)d_in[3];
    const float* w2    = (const float*)d_in[4];
    const float* b2    = (const float*)d_in[5];
    float* out = (float*)d_out;

    const int n_tok = in_sizes[0] / 8;                 // B*S tokens
    const int tok_per_blk = BLK * TPT;
    const int blocks = (n_tok + tok_per_blk - 1) / tok_per_blk;

    ffq_kernel<<<blocks, BLK>>>(x, theta, w1, b1, w2, b2, out, n_tok);
}